// round 10
// baseline (speedup 1.0000x reference)
#include <cuda_runtime.h>
#include <cuda_bf16.h>
#include <cstdint>

#define N_NODES 50000
#define N_EDGES 800000
#define D 128
#define NSCAN_BLK 196                     // ceil(50000/256)

// ---------------------------------------------------------------------------
// Scratch
__device__ int   g_is64;                  // edge_index dtype flag
__device__ __nv_bfloat16 g_B[4][D * D];   // W_rel hi/lo, W_root hi/lo
__device__ int g_hist[N_NODES];
__device__ int g_excl[N_NODES];
__device__ int g_bsum[NSCAN_BLK];
__device__ int g_bsum_scan[NSCAN_BLK];
__device__ int g_row_ptr[N_NODES + 1];
__device__ int g_cursor[N_NODES];
__device__ int g_src_sorted[N_EDGES];

// ---------------------------------------------------------------------------
__device__ __forceinline__ uint32_t smem_u32(const void* p) {
    uint32_t a;
    asm("{ .reg .u64 t; cvta.to.shared.u64 t, %1; cvt.u32.u64 %0, t; }" : "=r"(a) : "l"(p));
    return a;
}
__device__ __forceinline__ void ldsm_x4(uint32_t* r, uint32_t addr) {
    asm volatile("ldmatrix.sync.aligned.m8n8.x4.shared.b16 {%0,%1,%2,%3}, [%4];"
        : "=r"(r[0]), "=r"(r[1]), "=r"(r[2]), "=r"(r[3]) : "r"(addr));
}
__device__ __forceinline__ void mma16816(float* c, const uint32_t* a,
                                         uint32_t b0, uint32_t b1) {
    asm volatile("mma.sync.aligned.m16n8k16.row.col.f32.bf16.bf16.f32 "
        "{%0,%1,%2,%3}, {%4,%5,%6,%7}, {%8,%9}, {%0,%1,%2,%3};"
        : "+f"(c[0]), "+f"(c[1]), "+f"(c[2]), "+f"(c[3])
        : "r"(a[0]), "r"(a[1]), "r"(a[2]), "r"(a[3]), "r"(b0), "r"(b1));
}

// ---------------------------------------------------------------------------
__global__ void detect_dtype_kernel(const int* __restrict__ ei32) {
    if (threadIdx.x == 0 && blockIdx.x == 0) {
        int looks64 = 1;
        #pragma unroll
        for (int i = 1; i < 64; i += 2)
            if (ei32[i] != 0) looks64 = 0;
        g_is64 = looks64;
    }
}

__global__ void zero_hist_kernel() {
    int i = blockIdx.x * blockDim.x + threadIdx.x;
    if (i < N_NODES) g_hist[i] = 0;
}

__global__ void build_B_kernel(const float* __restrict__ W_rel,
                               const float* __restrict__ W_root) {
    int idx = blockIdx.x * blockDim.x + threadIdx.x;
    if (idx >= 2 * D * D) return;
    int h = idx >> 14;
    int r = idx & 16383;
    float v = h ? W_root[r] : W_rel[r];
    __nv_bfloat16 hi = __float2bfloat16(v);
    __nv_bfloat16 lo = __float2bfloat16(v - __bfloat162float(hi));
    g_B[2 * h + 0][r] = hi;
    g_B[2 * h + 1][r] = lo;
}

// ---- counting sort by dst --------------------------------------------------
// hist: 4 edges per thread, vectorized dst loads (MLP=2..4)
__global__ __launch_bounds__(256) void hist_kernel(const void* __restrict__ ei) {
    int t = blockIdx.x * blockDim.x + threadIdx.x;   // handles edges 4t..4t+3
    int e0 = t * 4;
    if (e0 >= N_EDGES) return;
    int d0, d1, d2, d3;
    if (g_is64) {
        const int4* p = reinterpret_cast<const int4*>((const long long*)ei + N_EDGES + e0);
        int4 a = p[0];       // edges e0, e0+1 (lo words at .x, .z)
        int4 b = p[1];       // edges e0+2, e0+3
        d0 = a.x; d1 = a.z; d2 = b.x; d3 = b.z;
    } else {
        int4 a = *reinterpret_cast<const int4*>((const int*)ei + N_EDGES + e0);
        d0 = a.x; d1 = a.y; d2 = a.z; d3 = a.w;
    }
    atomicAdd(&g_hist[d0], 1);
    atomicAdd(&g_hist[d1], 1);
    atomicAdd(&g_hist[d2], 1);
    atomicAdd(&g_hist[d3], 1);
}

__global__ __launch_bounds__(256) void scan1_kernel() {
    __shared__ int sh[256];
    int i = blockIdx.x * 256 + threadIdx.x;
    int v = (i < N_NODES) ? g_hist[i] : 0;
    sh[threadIdx.x] = v;
    __syncthreads();
    #pragma unroll
    for (int off = 1; off < 256; off <<= 1) {
        int t = (threadIdx.x >= off) ? sh[threadIdx.x - off] : 0;
        __syncthreads();
        sh[threadIdx.x] += t;
        __syncthreads();
    }
    int incl = sh[threadIdx.x];
    if (i < N_NODES) g_excl[i] = incl - v;
    if (threadIdx.x == 255) g_bsum[blockIdx.x] = incl;
}

__global__ __launch_bounds__(256) void scan2_kernel() {
    __shared__ int sh[256];
    int v = (threadIdx.x < NSCAN_BLK) ? g_bsum[threadIdx.x] : 0;
    sh[threadIdx.x] = v;
    __syncthreads();
    #pragma unroll
    for (int off = 1; off < 256; off <<= 1) {
        int t = (threadIdx.x >= off) ? sh[threadIdx.x - off] : 0;
        __syncthreads();
        sh[threadIdx.x] += t;
        __syncthreads();
    }
    if (threadIdx.x < NSCAN_BLK) g_bsum_scan[threadIdx.x] = sh[threadIdx.x] - v;
}

__global__ __launch_bounds__(256) void scan3_kernel() {
    int i = blockIdx.x * 256 + threadIdx.x;
    if (i < N_NODES) {
        int rp = g_excl[i] + g_bsum_scan[i >> 8];
        g_row_ptr[i] = rp;
        g_cursor[i]  = rp;
        if (i == 0) g_row_ptr[N_NODES] = N_EDGES;
    }
}

// permute: 2 edges per thread, vectorized loads
__global__ __launch_bounds__(256) void permute_kernel(const void* __restrict__ ei) {
    int t = blockIdx.x * blockDim.x + threadIdx.x;
    int e0 = t * 2;
    if (e0 >= N_EDGES) return;
    int s0, s1, d0, d1;
    if (g_is64) {
        int4 sa = *reinterpret_cast<const int4*>((const long long*)ei + e0);
        int4 da = *reinterpret_cast<const int4*>((const long long*)ei + N_EDGES + e0);
        s0 = sa.x; s1 = sa.z; d0 = da.x; d1 = da.z;
    } else {
        int2 sa = *reinterpret_cast<const int2*>((const int*)ei + e0);
        int2 da = *reinterpret_cast<const int2*>((const int*)ei + N_EDGES + e0);
        s0 = sa.x; s1 = sa.y; d0 = da.x; d1 = da.y;
    }
    int p0 = atomicAdd(&g_cursor[d0], 1);
    g_src_sorted[p0] = s0;
    int p1 = atomicAdd(&g_cursor[d1], 1);
    g_src_sorted[p1] = s1;
}

// ---------------------------------------------------------------------------
// FUSED: aggregation + HMMA bf16x3 dual-GEMM + bias + ReLU
//   acc  = x_tile @ W_root^T          (phase 1)
//   agg rows gathered straight into A smem as bf16 hi/lo (phase 2)
//   acc += agg_tile @ W_rel^T         (phase 3), then +bias, ReLU, store
#define LDA   136
#define TILE_B (128 * LDA * 2)
#define AS_HI  0
#define AS_LO  TILE_B
#define BS(b)  (2 * TILE_B + (b) * TILE_B)
#define SM_TOTAL (6 * TILE_B)             // 208896 bytes

__device__ __forceinline__ void mma_pass(const uint32_t sb, const uint32_t bs_hi,
                                         const uint32_t bs_lo, float acc[2][8][4],
                                         int wm, int wn, int lane) {
    const int arow = (lane & 15);
    const int acol = (lane >> 4) * 8;
    #pragma unroll
    for (int kk = 0; kk < 8; kk++) {
        const int kbase = kk * 16 + acol;
        uint32_t ah[2][4], al[2][4];
        #pragma unroll
        for (int mt = 0; mt < 2; mt++) {
            uint32_t off = (uint32_t)((wm * 32 + mt * 16 + arow) * LDA + kbase) * 2;
            ldsm_x4(ah[mt], sb + AS_HI + off);
            ldsm_x4(al[mt], sb + AS_LO + off);
        }
        #pragma unroll
        for (int ng = 0; ng < 4; ng++) {
            uint32_t boff = (uint32_t)((wn * 64 + ng * 16 + arow) * LDA + kbase) * 2;
            uint32_t bh[4], bl[4];
            ldsm_x4(bh, bs_hi + boff);
            ldsm_x4(bl, bs_lo + boff);
            #pragma unroll
            for (int mt = 0; mt < 2; mt++) {
                mma16816(acc[mt][2 * ng + 0], ah[mt], bh[0], bh[2]);
                mma16816(acc[mt][2 * ng + 1], ah[mt], bh[1], bh[3]);
                mma16816(acc[mt][2 * ng + 0], ah[mt], bl[0], bl[2]);
                mma16816(acc[mt][2 * ng + 1], ah[mt], bl[1], bl[3]);
                mma16816(acc[mt][2 * ng + 0], al[mt], bh[0], bh[2]);
                mma16816(acc[mt][2 * ng + 1], al[mt], bh[1], bh[3]);
            }
        }
    }
}

__global__ __launch_bounds__(256, 1) void gemm_fused_kernel(
    const float* __restrict__ x,
    const float* __restrict__ bias,
    float*       __restrict__ out) {
    extern __shared__ char smem[];
    const uint32_t sb  = smem_u32(smem);
    const int tid  = threadIdx.x;
    const int wid  = tid >> 5;
    const int lane = tid & 31;
    const int wm   = wid & 3;
    const int wn   = wid >> 2;
    const int m0   = blockIdx.x * 128;

    // ---- Stage all 4 B images ---------------------------------------------
    #pragma unroll
    for (int b = 0; b < 4; b++) {
        const uint4* src = reinterpret_cast<const uint4*>(&g_B[b][0]);
        #pragma unroll
        for (int i = 0; i < 8; i++) {
            int c  = tid + i * 256;
            int n  = c >> 4;
            int k8 = (c & 15) * 8;
            uint4 v = src[c];
            *reinterpret_cast<uint4*>(smem + BS(b) + (n * LDA + k8) * 2) = v;
        }
    }

    float acc[2][8][4];
    #pragma unroll
    for (int i = 0; i < 2; i++)
        #pragma unroll
        for (int j = 0; j < 8; j++)
            #pragma unroll
            for (int q = 0; q < 4; q++) acc[i][j][q] = 0.f;

    // ---- Phase 1: stage x tile, MMA with W_root ---------------------------
    {
        int r  = tid >> 1;
        int c0 = (tid & 1) * 64;
        int m  = m0 + r;
        if (m >= N_NODES) m = N_NODES - 1;
        const float4* row4 = reinterpret_cast<const float4*>(x + (size_t)m * D + c0);
        #pragma unroll
        for (int j = 0; j < 8; j++) {
            float4 f0 = row4[j * 2 + 0];
            float4 f1 = row4[j * 2 + 1];
            float f[8] = {f0.x, f0.y, f0.z, f0.w, f1.x, f1.y, f1.z, f1.w};
            uint32_t hi[4], lo[4];
            #pragma unroll
            for (int q = 0; q < 4; q++) {
                float a = f[2 * q], b = f[2 * q + 1];
                __nv_bfloat162 h2 = __floats2bfloat162_rn(a, b);
                float la = a - __bfloat162float(__low2bfloat16(h2));
                float lb = b - __bfloat162float(__high2bfloat16(h2));
                __nv_bfloat162 l2 = __floats2bfloat162_rn(la, lb);
                hi[q] = *reinterpret_cast<uint32_t*>(&h2);
                lo[q] = *reinterpret_cast<uint32_t*>(&l2);
            }
            uint32_t off = (uint32_t)(r * LDA + c0 + j * 8) * 2;
            *reinterpret_cast<uint4*>(smem + AS_HI + off) = make_uint4(hi[0], hi[1], hi[2], hi[3]);
            *reinterpret_cast<uint4*>(smem + AS_LO + off) = make_uint4(lo[0], lo[1], lo[2], lo[3]);
        }
    }
    __syncthreads();
    mma_pass(sb, sb + BS(2), sb + BS(3), acc, wm, wn, lane);
    __syncthreads();   // MMA reads done before As is overwritten

    // ---- Phase 2: aggregate 128 nodes straight into As --------------------
    // warp w handles rows w*16 .. w*16+15; lane covers cols lane*4..lane*4+3
    {
        const float4* x4 = reinterpret_cast<const float4*>(x);
        #pragma unroll 1
        for (int i = 0; i < 16; i++) {
            int r = wid * 16 + i;
            int m = m0 + r;
            float4 acc4 = make_float4(0.f, 0.f, 0.f, 0.f);
            if (m < N_NODES) {
                int beg = g_row_ptr[m];
                int end = g_row_ptr[m + 1];
                for (int j0 = beg; j0 < end; j0 += 32) {
                    int cnt = min(32, end - j0);
                    int myidx = (j0 + lane < end) ? g_src_sorted[j0 + lane] : 0;
                    for (int t = 0; t < cnt; t++) {
                        int s = __shfl_sync(0xffffffffu, myidx, t);
                        float4 v = x4[(size_t)s * 32 + lane];
                        acc4.x += v.x; acc4.y += v.y; acc4.z += v.z; acc4.w += v.w;
                    }
                }
            }
            // fp32 -> bf16 hi/lo, store 8B each
            __nv_bfloat162 h0 = __floats2bfloat162_rn(acc4.x, acc4.y);
            __nv_bfloat162 h1 = __floats2bfloat162_rn(acc4.z, acc4.w);
            float l0a = acc4.x - __bfloat162float(__low2bfloat16(h0));
            float l0b = acc4.y - __bfloat162float(__high2bfloat16(h0));
            float l1a = acc4.z - __bfloat162float(__low2bfloat16(h1));
            float l1b = acc4.w - __bfloat162float(__high2bfloat16(h1));
            __nv_bfloat162 lo0 = __floats2bfloat162_rn(l0a, l0b);
            __nv_bfloat162 lo1 = __floats2bfloat162_rn(l1a, l1b);
            uint32_t off = (uint32_t)(r * LDA + lane * 4) * 2;
            *reinterpret_cast<uint2*>(smem + AS_HI + off) =
                make_uint2(*reinterpret_cast<uint32_t*>(&h0), *reinterpret_cast<uint32_t*>(&h1));
            *reinterpret_cast<uint2*>(smem + AS_LO + off) =
                make_uint2(*reinterpret_cast<uint32_t*>(&lo0), *reinterpret_cast<uint32_t*>(&lo1));
        }
    }
    __syncthreads();

    // ---- Phase 3: MMA with W_rel ------------------------------------------
    mma_pass(sb, sb + BS(0), sb + BS(1), acc, wm, wn, lane);

    // ---- Epilogue: + bias, ReLU, store ------------------------------------
    #pragma unroll
    for (int mt = 0; mt < 2; mt++) {
        int r0 = m0 + wm * 32 + mt * 16 + (lane >> 2);
        #pragma unroll
        for (int nt = 0; nt < 8; nt++) {
            int n = wn * 64 + nt * 8 + (lane & 3) * 2;
            float2 bb = __ldg(reinterpret_cast<const float2*>(bias + n));
            float* a4 = acc[mt][nt];
            if (r0 < N_NODES) {
                float2 v;
                v.x = a4[0] + bb.x; v.y = a4[1] + bb.y;
                v.x = v.x > 0.f ? v.x : 0.f;
                v.y = v.y > 0.f ? v.y : 0.f;
                *reinterpret_cast<float2*>(out + (size_t)r0 * D + n) = v;
            }
            if (r0 + 8 < N_NODES) {
                float2 v;
                v.x = a4[2] + bb.x; v.y = a4[3] + bb.y;
                v.x = v.x > 0.f ? v.x : 0.f;
                v.y = v.y > 0.f ? v.y : 0.f;
                *reinterpret_cast<float2*>(out + (size_t)(r0 + 8) * D + n) = v;
            }
        }
    }
}

// ---------------------------------------------------------------------------
extern "C" void kernel_launch(void* const* d_in, const int* in_sizes, int n_in,
                              void* d_out, int out_size) {
    const float* x      = (const float*)d_in[0];
    const void*  ei     = d_in[1];
    const float* W_rel  = (const float*)d_in[2];
    const float* b_rel  = (const float*)d_in[3];
    const float* W_root = (const float*)d_in[4];
    float*       out    = (float*)d_out;

    cudaFuncSetAttribute(gemm_fused_kernel,
                         cudaFuncAttributeMaxDynamicSharedMemorySize, SM_TOTAL);

    detect_dtype_kernel<<<1, 32>>>((const int*)ei);
    zero_hist_kernel<<<NSCAN_BLK, 256>>>();
    build_B_kernel<<<(2 * D * D + 255) / 256, 256>>>(W_rel, W_root);

    hist_kernel<<<(N_EDGES / 4 + 255) / 256, 256>>>(ei);
    scan1_kernel<<<NSCAN_BLK, 256>>>();
    scan2_kernel<<<1, 256>>>();
    scan3_kernel<<<NSCAN_BLK, 256>>>();
    permute_kernel<<<(N_EDGES / 2 + 255) / 256, 256>>>(ei);

    {
        int blocks = (N_NODES + 127) / 128;
        gemm_fused_kernel<<<blocks, 256, SM_TOTAL>>>(x, b_rel, out);
    }
}